// round 2
// baseline (speedup 1.0000x reference)
#include <cuda_runtime.h>
#include <math.h>

// Problem constants (all shapes fixed by the dataset)
#define HH   768
#define TT   512
#define NCC  8
#define NLL  8921
#define NCTT 4096
#define NNN  4

#define ENC_RB  64
#define ENC_NRB (NCTT / ENC_RB)              // 64 row-blocks of encoding
#define LW_RB   64
#define LW_NRB  ((NLL + LW_RB - 1) / LW_RB)  // 140 row-blocks of label_weights

// Deterministic per-block partials (no atomics, every slot written each call)
__device__ float g_Cpart[ENC_NRB][HH];   // encoding row-block column sums
__device__ float g_Gpart[LW_NRB][HH];    // label_weights row-block column sums (pre-boundary part)
__device__ float g_Gfix[NCC][HH];        // post-boundary remainder of the block containing jsplit_c

// j-range boundaries: jsplit_c = ceil((512c-1)*8921/4096), jmax_c = ceil(512c*8921/4096)-1
__device__ __host__ __forceinline__ int jsplit_f(int c) {
    return (int)(((512LL * c - 1) * 8921 + 4095) >> 12);
}
__device__ __host__ __forceinline__ int jmax_f(int c) {
    return (int)(((512LL * c) * 8921 + 4095) >> 12) - 1;
}

// Fused streaming pass: blockIdx.x < ENC_NRB -> encoding partials, else label_weights partials.
__global__ void sums_kernel(const float* __restrict__ enc, const float* __restrict__ lw) {
    const int col = blockIdx.y * 256 + threadIdx.x;   // gridDim.y == 3 covers 768 cols

    if (blockIdx.x < ENC_NRB) {
        const int rb = blockIdx.x;
        const float* p = enc + (size_t)rb * ENC_RB * HH + col;
        float a0 = 0.f, a1 = 0.f, a2 = 0.f, a3 = 0.f;
#pragma unroll
        for (int r = 0; r < ENC_RB; r += 4) {
            a0 += p[(size_t)(r + 0) * HH];
            a1 += p[(size_t)(r + 1) * HH];
            a2 += p[(size_t)(r + 2) * HH];
            a3 += p[(size_t)(r + 3) * HH];
        }
        g_Cpart[rb][col] = (a0 + a1) + (a2 + a3);
    } else {
        const int rb = blockIdx.x - ENC_NRB;
        const int r0 = rb * LW_RB;
        const int r1 = min(r0 + LW_RB, NLL);
        // segment of r0 and the next boundary after r0
        int seg = 0;
#pragma unroll
        for (int c = 1; c <= 7; c++)
            if (jsplit_f(c) <= r0) seg = c;
        const int nb   = (seg < 7) ? jsplit_f(seg + 1) : NLL;
        const int rmid = min(r1, nb);

        const float* p = lw + (size_t)r0 * HH + col;
        float acc = 0.f;
        for (int r = r0; r < rmid; r++) { acc += *p; p += HH; }
        g_Gpart[rb][col] = acc;
        if (nb < r1) {  // block straddles a segment boundary: remainder goes to seg+1
            acc = 0.f;
            for (int r = nb; r < r1; r++) { acc += *p; p += HH; }
            g_Gfix[seg + 1][col] = acc;
        }
    }
}

__global__ void combine_kernel(const float* __restrict__ lw,
                               const int* __restrict__ ids_raw,
                               float* __restrict__ out) {
    const int h = blockIdx.x * blockDim.x + threadIdx.x;
    if (h >= HH) return;

    // --- decode note_end_chunk_ids: handle int32 (JAX default) or genuine int64 ---
    int ids[NNN];
    {
        const int a0 = ids_raw[0], a1 = ids_raw[1], a2 = ids_raw[2], a3 = ids_raw[3];
        const bool ok32 = (a0 >= 0) && (a0 <= a1) && (a1 <= a2) && (a2 <= a3) && (a3 < NCC);
        if (ok32) {
            ids[0] = a0; ids[1] = a1; ids[2] = a2; ids[3] = a3;
        } else {
            const long long* q = (const long long*)ids_raw;
            ids[0] = (int)q[0]; ids[1] = (int)q[1]; ids[2] = (int)q[2]; ids[3] = (int)q[3];
        }
    }

    // --- prefix sums of encoding at chunk boundaries: P[c] = sum of rows [0, 512c) ---
    float P[NCC + 1];
    P[0] = 0.f;
#pragma unroll
    for (int c = 0; c < NCC; c++) {
        float s = 0.f;
#pragma unroll
        for (int k = 0; k < ENC_NRB / NCC; k++)
            s += g_Cpart[c * (ENC_NRB / NCC) + k][h];
        P[c + 1] = P[c] + s;
    }
    const float Ptot = P[NCC];

    // --- segment sums of label_weights (viewed (NL, H) row-major) over the 8 j-groups ---
    float G[NCC];
#pragma unroll
    for (int c = 0; c < NCC; c++) G[c] = 0.f;
    for (int rb = 0; rb < LW_NRB; rb++) {
        const int r0 = rb * LW_RB;
        const int r1 = min(r0 + LW_RB, NLL);
        int seg = 0;
#pragma unroll
        for (int c = 1; c <= 7; c++)
            if (jsplit_f(c) <= r0) seg = c;
        G[seg] += g_Gpart[rb][h];
        const int nb = (seg < 7) ? jsplit_f(seg + 1) : NLL;
        if (nb < r1) G[seg + 1] += g_Gfix[seg + 1][h];
    }

    // --- sparse boundary rows of lw: A_c = lw[jmax_c], E_c = sum of lw[jsplit_c .. jmax_c-1] ---
    float A[8], E[8];
#pragma unroll
    for (int c = 1; c <= 7; c++) {
        const int js = jsplit_f(c), jm = jmax_f(c);
        A[c] = lw[(size_t)jm * HH + h];
        float e = 0.f;
        for (int j = js; j < jm; j++) e += lw[(size_t)j * HH + h];
        E[c] = e;
    }

    // --- note-weight table: W[n][c] = softmax-over-notes weight for positions in chunk c ---
    float W[NNN][NCC];
#pragma unroll
    for (int c = 0; c < NCC; c++) {
        int cnt = 0;
#pragma unroll
        for (int m = 0; m < NNN; m++) cnt += (ids[m] < c) ? 1 : 0;
        const float inv = (cnt > 0) ? (1.f / (float)cnt) : 0.f;
#pragma unroll
        for (int n = 0; n < NNN; n++)
            W[n][c] = (cnt == 0) ? (1.f / NNN) : ((ids[n] < c) ? inv : 0.f);
    }

    // --- final combine: score[n,h] = SP + Ptot * D ; out = sigmoid(score) ---
#pragma unroll
    for (int n = 0; n < NNN; n++) {
        float D = 0.f, SP = 0.f;
#pragma unroll
        for (int c = 0; c < NCC; c++) D += W[n][c] * G[c];
#pragma unroll
        for (int c = 1; c <= 7; c++) {
            const float dW = W[n][c - 1] - W[n][c];
            SP += dW * (A[c] * P[c] + E[c] * Ptot);
        }
        const float s = SP + Ptot * D;
        out[n * HH + h] = 1.f / (1.f + expf(-s));
    }
}

extern "C" void kernel_launch(void* const* d_in, const int* in_sizes, int n_in,
                              void* d_out, int out_size) {
    const float* enc = (const float*)d_in[0];   // encoding (4096, 768) f32
    const float* lw  = (const float*)d_in[2];   // label_weights buffer (768*8921) f32, viewed (8921, 768)
    const int*   ids = (const int*)d_in[3];     // note_end_chunk_ids (4,) int32 or int64
    float* out = (float*)d_out;                 // (4, 768) f32
    (void)in_sizes; (void)n_in; (void)out_size; // label_queries (d_in[1]) is provably unused

    dim3 grid(ENC_NRB + LW_NRB, 3);
    sums_kernel<<<grid, 256>>>(enc, lw);
    combine_kernel<<<3, 256>>>(lw, ids, out);
}

// round 6
// speedup vs baseline: 1.3254x; 1.3254x over previous
#include <cuda_runtime.h>
#include <math.h>

// Problem constants (all shapes fixed by the dataset)
#define HH   768
#define TT   512
#define NCC  8
#define NLL  8921
#define NCTT 4096
#define NNN  4

#define ENC_RB  64
#define ENC_NRB (NCTT / ENC_RB)              // 64 row-blocks of encoding
#define LW_RB   64
#define LW_NRB  ((NLL + LW_RB - 1) / LW_RB)  // 140 row-blocks of label_weights

// Deterministic per-block partials (no atomics, every slot written each call)
__device__ float g_Cpart[ENC_NRB][HH];   // encoding row-block column sums
__device__ float g_Gpart[LW_NRB][HH];    // label_weights row-block column sums (pre-boundary part)
__device__ float g_Gfix[NCC][HH];        // post-boundary remainder of the straddling block

// j-range boundaries: jsplit_c = ceil((512c-1)*8921/4096), jmax_c = ceil(512c*8921/4096)-1
__device__ __host__ __forceinline__ int jsplit_f(int c) {
    return (int)(((512LL * c - 1) * 8921 + 4095) >> 12);
}
__device__ __host__ __forceinline__ int jmax_f(int c) {
    return (int)(((512LL * c) * 8921 + 4095) >> 12) - 1;
}

// Fused streaming pass: blockIdx.x < ENC_NRB -> encoding partials, else label_weights partials.
__global__ void sums_kernel(const float* __restrict__ enc, const float* __restrict__ lw) {
    const int col = blockIdx.y * 256 + threadIdx.x;   // gridDim.y == 3 covers 768 cols

    if (blockIdx.x < ENC_NRB) {
        const int rb = blockIdx.x;
        const float* p = enc + (size_t)rb * ENC_RB * HH + col;
        float a0 = 0.f, a1 = 0.f, a2 = 0.f, a3 = 0.f;
#pragma unroll
        for (int r = 0; r < ENC_RB; r += 4) {
            a0 += p[(size_t)(r + 0) * HH];
            a1 += p[(size_t)(r + 1) * HH];
            a2 += p[(size_t)(r + 2) * HH];
            a3 += p[(size_t)(r + 3) * HH];
        }
        g_Cpart[rb][col] = (a0 + a1) + (a2 + a3);
    } else {
        const int rb = blockIdx.x - ENC_NRB;
        const int r0 = rb * LW_RB;
        const int r1 = min(r0 + LW_RB, NLL);
        int seg = 0;
#pragma unroll
        for (int c = 1; c <= 7; c++)
            if (jsplit_f(c) <= r0) seg = c;
        const int nb   = (seg < 7) ? jsplit_f(seg + 1) : NLL;
        const int rmid = min(r1, nb);

        const float* p = lw + (size_t)r0 * HH + col;
        float acc = 0.f;
        for (int r = r0; r < rmid; r++) { acc += *p; p += HH; }
        g_Gpart[rb][col] = acc;
        if (nb < r1) {  // block straddles a segment boundary: remainder goes to seg+1
            acc = 0.f;
            for (int r = nb; r < r1; r++) { acc += *p; p += HH; }
            g_Gfix[seg + 1][col] = acc;
        }
    }
}

// Parallel reduction + tiny algebra. 12 blocks x 256 threads.
// Each block owns 64 h-columns; 4 "slices" per column stride the partial arrays.
__global__ void combine_kernel(const float* __restrict__ lw,
                               const int* __restrict__ ids_raw,
                               float* __restrict__ out) {
    const int hl    = threadIdx.x & 63;
    const int slice = threadIdx.x >> 6;          // 0..3
    const int h     = blockIdx.x * 64 + hl;

    // --- lw segment partial reduction: 35 independent loads per thread ---
    float segG[8];
#pragma unroll
    for (int c = 0; c < 8; c++) segG[c] = 0.f;
#pragma unroll 5
    for (int rb = slice; rb < LW_NRB; rb += 4) {
        const float v = g_Gpart[rb][h];
        const int r0 = rb * LW_RB;
        int seg = 0;
#pragma unroll
        for (int c = 1; c <= 7; c++) seg += (jsplit_f(c) <= r0) ? 1 : 0;
#pragma unroll
        for (int c = 0; c < 8; c++) segG[c] += (seg == c) ? v : 0.f;
    }
    // straddle remainders (all 7 boundaries verified non-64-aligned -> always written)
#pragma unroll
    for (int c = 1; c <= 7; c++)
        if (((c - 1) & 3) == slice) segG[c] += g_Gfix[c][h];

    // --- encoding chunk sums: constant indexing, 2 loads per slice per chunk ---
    float chunkS[8];
#pragma unroll
    for (int c = 0; c < 8; c++)
        chunkS[c] = g_Cpart[8 * c + 2 * slice][h] + g_Cpart[8 * c + 2 * slice + 1][h];

    // --- boundary rows of lw: A_c = lw[jmax_c], E_c = sum of lw[jsplit_c .. jmax_c-1] ---
    __shared__ float sA[8][64];
    __shared__ float sE[8][64];
#pragma unroll
    for (int c = 1; c <= 7; c++) {
        if (((c - 1) & 3) == slice) {
            const int js = jsplit_f(c), jm = jmax_f(c);
            sA[c][hl] = lw[(size_t)jm * HH + h];
            float e = 0.f;
            for (int j = js; j < jm; j++) e += lw[(size_t)j * HH + h];
            sE[c][hl] = e;
        }
    }

    // --- cross-slice reduction through padded smem (conflict-free) ---
    __shared__ float sRed[4][64][17];
#pragma unroll
    for (int c = 0; c < 8; c++) {
        sRed[slice][hl][c]     = segG[c];
        sRed[slice][hl][8 + c] = chunkS[c];
    }
    __syncthreads();

    if (slice == 0) {
        float G[8], S[8];
#pragma unroll
        for (int c = 0; c < 8; c++) {
            G[c] = (sRed[0][hl][c] + sRed[1][hl][c]) + (sRed[2][hl][c] + sRed[3][hl][c]);
            S[c] = (sRed[0][hl][8 + c] + sRed[1][hl][8 + c]) +
                   (sRed[2][hl][8 + c] + sRed[3][hl][8 + c]);
        }
        float P[NCC + 1];
        P[0] = 0.f;
#pragma unroll
        for (int c = 0; c < NCC; c++) P[c + 1] = P[c] + S[c];
        const float Ptot = P[NCC];

        // decode note_end_chunk_ids: int32 (JAX default) or genuine int64
        int ids[NNN];
        {
            const int a0 = ids_raw[0], a1 = ids_raw[1], a2 = ids_raw[2], a3 = ids_raw[3];
            const bool ok32 = (a0 >= 0) && (a0 <= a1) && (a1 <= a2) && (a2 <= a3) && (a3 < NCC);
            if (ok32) {
                ids[0] = a0; ids[1] = a1; ids[2] = a2; ids[3] = a3;
            } else {
                const long long* q = (const long long*)ids_raw;
                ids[0] = (int)q[0]; ids[1] = (int)q[1]; ids[2] = (int)q[2]; ids[3] = (int)q[3];
            }
        }

        // note-weight table: W[n][c] = softmax-over-notes weight for positions in chunk c
        float W[NNN][NCC];
#pragma unroll
        for (int c = 0; c < NCC; c++) {
            int cnt = 0;
#pragma unroll
            for (int m = 0; m < NNN; m++) cnt += (ids[m] < c) ? 1 : 0;
            const float inv = (cnt > 0) ? (1.f / (float)cnt) : 0.f;
#pragma unroll
            for (int n = 0; n < NNN; n++)
                W[n][c] = (cnt == 0) ? (1.f / NNN) : ((ids[n] < c) ? inv : 0.f);
        }

        // final: score[n,h] = sum_c W*G*Ptot-terms + boundary corrections; out = sigmoid
#pragma unroll
        for (int n = 0; n < NNN; n++) {
            float D = 0.f, SP = 0.f;
#pragma unroll
            for (int c = 0; c < NCC; c++) D += W[n][c] * G[c];
#pragma unroll
            for (int c = 1; c <= 7; c++) {
                const float dW = W[n][c - 1] - W[n][c];
                SP += dW * (sA[c][hl] * P[c] + sE[c][hl] * Ptot);
            }
            const float s = SP + Ptot * D;
            out[n * HH + h] = 1.f / (1.f + expf(-s));
        }
    }
}

extern "C" void kernel_launch(void* const* d_in, const int* in_sizes, int n_in,
                              void* d_out, int out_size) {
    const float* enc = (const float*)d_in[0];   // encoding (4096, 768) f32
    const float* lw  = (const float*)d_in[2];   // label_weights buffer, viewed (8921, 768) f32
    const int*   ids = (const int*)d_in[3];     // note_end_chunk_ids (4,) int32 or int64
    float* out = (float*)d_out;                 // (4, 768) f32
    (void)in_sizes; (void)n_in; (void)out_size; // label_queries (d_in[1]) provably unused

    dim3 grid(ENC_NRB + LW_NRB, 3);
    sums_kernel<<<grid, 256>>>(enc, lw);
    combine_kernel<<<12, 256>>>(lw, ids, out);
}

// round 11
// speedup vs baseline: 1.4652x; 1.1055x over previous
#include <cuda_runtime.h>
#include <math.h>

// Problem constants (all shapes fixed by the dataset)
#define HH   768
#define H4   (HH / 4)       // 192 float4 per row
#define TT   512
#define NCC  8
#define NLL  8921
#define NCTT 4096
#define NNN  4

#define RB      32
#define ENC_NRB (NCTT / RB)                 // 128 row-blocks of encoding
#define LW_NRB  ((NLL + RB - 1) / RB)       // 279 row-blocks of label_weights

// Deterministic per-block partials (no atomics, every needed slot written each call)
__device__ float g_Cpart[ENC_NRB][HH];   // encoding row-block column sums
__device__ float g_Gpart[LW_NRB][HH];    // label_weights row-block column sums (pre-boundary part)
__device__ float g_Gfix[NCC][HH];        // post-boundary remainder of the straddling block

// j-range boundaries: jsplit_c = ceil((512c-1)*8921/4096), jmax_c = ceil(512c*8921/4096)-1
__device__ __host__ __forceinline__ int jsplit_f(int c) {
    return (int)(((512LL * c - 1) * 8921 + 4095) >> 12);
}

// Compile-time tables (derived from jsplit/jmax; verified against jsplit_f):
// segment c owns Gpart rows rb in [RB_LO[c], RB_HI[c])
__constant__ int c_RB_LO[8] = {0, 35, 70, 105, 140, 175, 210, 244};
__constant__ int c_RB_HI[8] = {35, 70, 105, 140, 175, 210, 244, 279};
__constant__ int c_JS[8]    = {0, 1113, 2229, 3344, 4459, 5574, 6689, 7804};
__constant__ int c_JM[8]    = {0, 1115, 2230, 3345, 4460, 5575, 6690, 7805};

// Fused streaming pass (float4): blockIdx.x < ENC_NRB -> encoding, else label_weights.
// 192 threads: thread t owns float4 column t (covers all 768 scalar cols).
__global__ void sums_kernel(const float4* __restrict__ enc, const float4* __restrict__ lw) {
    const int t = threadIdx.x;

    if (blockIdx.x < ENC_NRB) {
        const int rb = blockIdx.x;
        const float4* p = enc + (size_t)rb * RB * H4 + t;
        float4 a = make_float4(0.f, 0.f, 0.f, 0.f);
        float4 b = make_float4(0.f, 0.f, 0.f, 0.f);
#pragma unroll
        for (int r = 0; r < RB; r += 2) {
            const float4 v0 = p[(size_t)r * H4];
            const float4 v1 = p[(size_t)(r + 1) * H4];
            a.x += v0.x; a.y += v0.y; a.z += v0.z; a.w += v0.w;
            b.x += v1.x; b.y += v1.y; b.z += v1.z; b.w += v1.w;
        }
        a.x += b.x; a.y += b.y; a.z += b.z; a.w += b.w;
        ((float4*)g_Cpart[rb])[t] = a;
    } else {
        const int rb = blockIdx.x - ENC_NRB;
        const int r0 = rb * RB;
        const int r1 = min(r0 + RB, NLL);
        int seg = 0;
#pragma unroll
        for (int c = 1; c <= 7; c++)
            if (jsplit_f(c) <= r0) seg = c;
        const int nb   = (seg < 7) ? jsplit_f(seg + 1) : NLL;
        const int rmid = min(r1, nb);

        const float4* p = lw + (size_t)r0 * H4 + t;
        float4 a = make_float4(0.f, 0.f, 0.f, 0.f);
        for (int r = r0; r < rmid; r++) {
            const float4 v = *p; p += H4;
            a.x += v.x; a.y += v.y; a.z += v.z; a.w += v.w;
        }
        ((float4*)g_Gpart[rb])[t] = a;
        if (nb < r1) {  // block straddles a segment boundary: remainder goes to seg+1
            a = make_float4(0.f, 0.f, 0.f, 0.f);
            for (int r = nb; r < r1; r++) {
                const float4 v = *p; p += H4;
                a.x += v.x; a.y += v.y; a.z += v.z; a.w += v.w;
            }
            ((float4*)g_Gfix[seg + 1])[t] = a;
        }
    }
}

// Reduction + algebra. 24 blocks x 256 threads = 32 h-cols x 8 slices.
// Slice s reduces segment s of g_Gpart, chunk s of g_Cpart, and segment s's
// boundary rows of lw -- all with zero runtime routing.
__global__ void combine_kernel(const float* __restrict__ lw,
                               const int* __restrict__ ids_raw,
                               float* __restrict__ out) {
    const int hl    = threadIdx.x & 31;
    const int slice = threadIdx.x >> 5;          // 0..7 == segment / chunk id
    const int h     = blockIdx.x * 32 + hl;

    // --- segment sum of label_weights partials: <=35 independent predicated loads ---
    const int lo = c_RB_LO[slice];
    const int hi = c_RB_HI[slice];
    float g0 = 0.f, g1 = 0.f, g2 = 0.f, g3 = 0.f;
#pragma unroll
    for (int i = 0; i < 36; i += 4) {
        if (lo + i + 0 < hi) g0 += g_Gpart[lo + i + 0][h];
        if (lo + i + 1 < hi) g1 += g_Gpart[lo + i + 1][h];
        if (lo + i + 2 < hi) g2 += g_Gpart[lo + i + 2][h];
        if (lo + i + 3 < hi) g3 += g_Gpart[lo + i + 3][h];
    }
    float segG = (g0 + g1) + (g2 + g3);
    if (slice >= 1) segG += g_Gfix[slice][h];    // straddle remainder (always written)

    // --- chunk sum: slice s owns encoding chunk s = Cpart rows [16s, 16s+16) ---
    float s0 = 0.f, s1 = 0.f;
#pragma unroll
    for (int k = 0; k < 16; k += 2) {
        s0 += g_Cpart[slice * 16 + k][h];
        s1 += g_Cpart[slice * 16 + k + 1][h];
    }
    const float chunkS = s0 + s1;

    // --- boundary rows of lw: A = lw[jmax], E = sum lw[jsplit..jmax-1] (<=2 rows) ---
    float A = 0.f, E = 0.f;
    if (slice >= 1) {
        const int js = c_JS[slice], jm = c_JM[slice];
        A = lw[(size_t)jm * HH + h];
        E = lw[(size_t)js * HH + h];
        if (js + 1 < jm) E += lw[(size_t)(js + 1) * HH + h];
    }

    // --- cross-slice exchange through smem (stride 5: conflict-free) ---
    __shared__ float sm[8][32][5];
    sm[slice][hl][0] = segG;
    sm[slice][hl][1] = chunkS;
    sm[slice][hl][2] = A;
    sm[slice][hl][3] = E;
    __syncthreads();

    if (slice == 0) {
        float G[8], S[8], Av[8], Ev[8];
#pragma unroll
        for (int c = 0; c < 8; c++) {
            G[c]  = sm[c][hl][0];
            S[c]  = sm[c][hl][1];
            Av[c] = sm[c][hl][2];
            Ev[c] = sm[c][hl][3];
        }
        float P[NCC + 1];
        P[0] = 0.f;
#pragma unroll
        for (int c = 0; c < NCC; c++) P[c + 1] = P[c] + S[c];
        const float Ptot = P[NCC];

        // decode note_end_chunk_ids: int32 (JAX default) or genuine int64
        int ids[NNN];
        {
            const int a0 = ids_raw[0], a1 = ids_raw[1], a2 = ids_raw[2], a3 = ids_raw[3];
            const bool ok32 = (a0 >= 0) && (a0 <= a1) && (a1 <= a2) && (a2 <= a3) && (a3 < NCC);
            if (ok32) {
                ids[0] = a0; ids[1] = a1; ids[2] = a2; ids[3] = a3;
            } else {
                const long long* q = (const long long*)ids_raw;
                ids[0] = (int)q[0]; ids[1] = (int)q[1]; ids[2] = (int)q[2]; ids[3] = (int)q[3];
            }
        }

        // note-weight table: W[n][c] = softmax-over-notes weight for positions in chunk c
        float W[NNN][NCC];
#pragma unroll
        for (int c = 0; c < NCC; c++) {
            int cnt = 0;
#pragma unroll
            for (int m = 0; m < NNN; m++) cnt += (ids[m] < c) ? 1 : 0;
            const float inv = (cnt > 0) ? (1.f / (float)cnt) : 0.f;
#pragma unroll
            for (int n = 0; n < NNN; n++)
                W[n][c] = (cnt == 0) ? (1.f / NNN) : ((ids[n] < c) ? inv : 0.f);
        }

        // final: score[n,h] = boundary corrections + Ptot-weighted segment sums
#pragma unroll
        for (int n = 0; n < NNN; n++) {
            float D = 0.f, SP = 0.f;
#pragma unroll
            for (int c = 0; c < NCC; c++) D += W[n][c] * G[c];
#pragma unroll
            for (int c = 1; c <= 7; c++) {
                const float dW = W[n][c - 1] - W[n][c];
                SP += dW * (Av[c] * P[c] + Ev[c] * Ptot);
            }
            const float s = SP + Ptot * D;
            out[n * HH + h] = 1.f / (1.f + expf(-s));
        }
    }
}

extern "C" void kernel_launch(void* const* d_in, const int* in_sizes, int n_in,
                              void* d_out, int out_size) {
    const float* enc = (const float*)d_in[0];   // encoding (4096, 768) f32 (16B-aligned)
    const float* lw  = (const float*)d_in[2];   // label_weights buffer, viewed (8921, 768) f32
    const int*   ids = (const int*)d_in[3];     // note_end_chunk_ids (4,) int32 or int64
    float* out = (float*)d_out;                 // (4, 768) f32
    (void)in_sizes; (void)n_in; (void)out_size; // label_queries (d_in[1]) provably unused

    sums_kernel<<<ENC_NRB + LW_NRB, H4>>>((const float4*)enc, (const float4*)lw);
    combine_kernel<<<24, 256>>>(lw, ids, out);
}